// round 12
// baseline (speedup 1.0000x reference)
#include <cuda_runtime.h>
#include <cuda_bf16.h>
#include <math.h>
#include <cstdint>

#define BATCH 4
#define SEQ 4096
#define CDIM 1024
#define HDIM 64
#define MROWS (BATCH * SEQ)   // 16384

// Scratch (no cudaMalloc allowed). g_q/g_k/g_v hold tf32-rounded floats;
// g_q additionally pre-scaled by 1/sqrt(64). g_wt = [1024][192] tf32 weights.
__device__ float g_q[(size_t)MROWS * HDIM];
__device__ float g_k[(size_t)MROWS * HDIM];
__device__ float g_v[(size_t)MROWS * HDIM];
__device__ float g_wt[(size_t)CDIM * 192];
__device__ float g_osc[2][(size_t)MROWS * HDIM];   // split partial O
__device__ float g_ml[2][(size_t)MROWS * 2];       // split (m, l)

// ---------------------------------------------------------------------------
// helpers
// ---------------------------------------------------------------------------
__device__ __forceinline__ uint32_t to_tf32(float f) {
    uint32_t r;
    asm("cvt.rna.tf32.f32 %0, %1;" : "=r"(r) : "f"(f));
    return r;
}
__device__ __forceinline__ void mma_tf32(float* c, const uint32_t* a, const uint32_t* b) {
    asm volatile(
        "mma.sync.aligned.m16n8k8.row.col.f32.tf32.tf32.f32 "
        "{%0,%1,%2,%3}, {%4,%5,%6,%7}, {%8,%9}, {%0,%1,%2,%3};\n"
        : "+f"(c[0]), "+f"(c[1]), "+f"(c[2]), "+f"(c[3])
        : "r"(a[0]), "r"(a[1]), "r"(a[2]), "r"(a[3]), "r"(b[0]), "r"(b[1]));
}
__device__ __forceinline__ float qmax(float v) {
    v = fmaxf(v, __shfl_xor_sync(0xffffffffu, v, 1));
    v = fmaxf(v, __shfl_xor_sync(0xffffffffu, v, 2));
    return v;
}
__device__ __forceinline__ float qsum(float v) {
    v += __shfl_xor_sync(0xffffffffu, v, 1);
    v += __shfl_xor_sync(0xffffffffu, v, 2);
    return v;
}
__device__ __forceinline__ void cp16(uint32_t smem_dst, const void* gmem_src) {
    asm volatile("cp.async.cg.shared.global [%0], [%1], 16;"
                 :: "r"(smem_dst), "l"(gmem_src));
}
#define CP_COMMIT() asm volatile("cp.async.commit_group;" ::: "memory")
#define CP_WAIT0()  asm volatile("cp.async.wait_group 0;" ::: "memory")

// ---------------------------------------------------------------------------
// prep_w: convert the three weight matrices to tf32, packed [1024][192]
// ---------------------------------------------------------------------------
__global__ __launch_bounds__(256) void prep_w(
    const float* __restrict__ Wq,
    const float* __restrict__ Wk,
    const float* __restrict__ Wv)
{
    int idx = blockIdx.x * 256 + threadIdx.x;
    int k = idx / 192;
    int c = idx % 192;
    const float* W = (c < 64) ? Wq : (c < 128) ? Wk : Wv;
    g_wt[idx] = __uint_as_float(to_tf32(W[k * HDIM + (c & 63)]));
}

// ---------------------------------------------------------------------------
// Fused projection: {q,k,v} = x @ [Wq|Wk|Wv]  (unchanged from R10)
// ---------------------------------------------------------------------------
#define FAS 36
#define FBS 200
#define FABUF (64 * FAS)
#define FBBUF (32 * FBS)
#define FBUF  (FABUF + FBBUF)
#define FPROJ_SMEM (2 * FBUF * 4)

__global__ __launch_bounds__(128) void proj_fused(const float* __restrict__ x)
{
    extern __shared__ float sm[];
    const uint32_t sbase = (uint32_t)__cvta_generic_to_shared(sm);

    const int tid = threadIdx.x;
    const int warp = tid >> 5;
    const int lane = tid & 31;
    const int grp = lane >> 2;
    const int tig = lane & 3;
    const int wm = warp >> 1;
    const int wn = warp & 1;
    const int row0 = blockIdx.x * 64;

    float acc[2][12][4];
#pragma unroll
    for (int m = 0; m < 2; m++)
#pragma unroll
        for (int j = 0; j < 12; j++)
#pragma unroll
            for (int e = 0; e < 4; e++) acc[m][j][e] = 0.0f;

    auto issue_tile = [&](int it, int buf) {
        const int kc = it * 32;
        const uint32_t ab = sbase + (uint32_t)(buf * FBUF) * 4u;
        const uint32_t bb = ab + (uint32_t)FABUF * 4u;
#pragma unroll
        for (int i = 0; i < 4; i++) {
            int id = tid + i * 128;
            int r = id >> 3;
            int c4 = id & 7;
            cp16(ab + (uint32_t)(r * FAS + c4 * 4) * 4u,
                 &x[(size_t)(row0 + r) * CDIM + kc + c4 * 4]);
        }
#pragma unroll
        for (int i = 0; i < 12; i++) {
            int id = tid + i * 128;
            int r = id / 48;
            int c = id % 48;
            cp16(bb + (uint32_t)(r * FBS + c * 4) * 4u,
                 &g_wt[(size_t)(kc + r) * 192 + c * 4]);
        }
        CP_COMMIT();
    };

    issue_tile(0, 0);

    for (int it = 0; it < 32; it++) {
        const int cur = it & 1;
        CP_WAIT0();
        __syncthreads();
        if (it < 31) issue_tile(it + 1, cur ^ 1);

        const float* As = sm + cur * FBUF;
        const float* Bs = As + FABUF;

#pragma unroll
        for (int ks = 0; ks < 4; ks++) {
            uint32_t a[8];
#pragma unroll
            for (int m = 0; m < 2; m++) {
                const int rb = 32 * wm + 16 * m;
                a[4 * m + 0] = to_tf32(As[(rb + grp) * FAS + 8 * ks + tig]);
                a[4 * m + 1] = to_tf32(As[(rb + grp + 8) * FAS + 8 * ks + tig]);
                a[4 * m + 2] = to_tf32(As[(rb + grp) * FAS + 8 * ks + tig + 4]);
                a[4 * m + 3] = to_tf32(As[(rb + grp + 8) * FAS + 8 * ks + tig + 4]);
            }
#pragma unroll
            for (int jj = 0; jj < 12; jj++) {
                const int col = 96 * wn + 8 * jj;
                uint32_t b[2];
                b[0] = __float_as_uint(Bs[(8 * ks + tig) * FBS + col + grp]);
                b[1] = __float_as_uint(Bs[(8 * ks + tig + 4) * FBS + col + grp]);
                mma_tf32(acc[0][jj], a, b);
                mma_tf32(acc[1][jj], a + 4, b);
            }
        }
        __syncthreads();
    }

#pragma unroll
    for (int m = 0; m < 2; m++) {
        const int row = row0 + 32 * wm + 16 * m + grp;
#pragma unroll
        for (int jj = 0; jj < 12; jj++) {
            const int gc = 96 * wn + 8 * jj;
            const int mat = gc >> 6;
            const int col = (gc & 63) + 2 * tig;
            float* out = (mat == 0) ? g_q : (mat == 1) ? g_k : g_v;
            const float scale = (mat == 0) ? 0.125f : 1.0f;
            float2 lo = make_float2(
                __uint_as_float(to_tf32(scale * acc[m][jj][0])),
                __uint_as_float(to_tf32(scale * acc[m][jj][1])));
            float2 hi = make_float2(
                __uint_as_float(to_tf32(scale * acc[m][jj][2])),
                __uint_as_float(to_tf32(scale * acc[m][jj][3])));
            *(float2*)&out[(size_t)row * HDIM + col] = lo;
            *(float2*)&out[(size_t)(row + 8) * HDIM + col] = hi;
        }
    }
}

// ---------------------------------------------------------------------------
// Attention: 128-row Q tiles, 4 warps x 32 rows (2 m16 subtiles per warp ->
// each K/V b-fragment load feeds 2 MMAs: halves crossbar bytes per MMA).
// cp.async double-buffered K/V. Pair (t, 31-t) + kb-parity split-2 -> 128
// equal CTAs of 128 threads. Key block kb is diagonal for kb in {2t, 2t+1}.
// ---------------------------------------------------------------------------
#define AQS 68
#define AVS 72
#define APS 68
#define QBUF (128 * AQS)
#define KBUF (64 * AQS)
#define VBUF (64 * AVS)
#define PBUF (128 * APS)
#define ATTN_SMEM ((QBUF + 2 * KBUF + 2 * VBUF + PBUF) * 4)

__device__ __forceinline__ void attn_tile_tc(
    int b, int t, int split,
    float* Qs, float* Ks, float* Vs, float* Ps,
    uint32_t qb32, uint32_t kb32, uint32_t vb32)
{
    const int tid = threadIdx.x;
    const int mg = tid >> 5;          // warp 0..3 -> rows 32*mg..32*mg+31
    const int lane = tid & 31;
    const int grp = lane >> 2;
    const int tig = lane & 3;
    const int rb = 32 * mg;

    const float* kbase = g_k + (size_t)b * SEQ * HDIM;
    const float* vbase = g_v + (size_t)b * SEQ * HDIM;
    const float* qb = g_q + ((size_t)b * SEQ + 128 * t) * HDIM;

    __syncthreads();   // previous tile done with all smem

    // ---- prologue: Q (128x64) + first K/V (64x64) into buffer 0 ----
#pragma unroll
    for (int i = 0; i < 16; i++) {
        int id = tid + i * 128;
        int r = id >> 4;              // 0..127
        int c4 = id & 15;
        cp16(qb32 + (uint32_t)(r * AQS + c4 * 4) * 4u,
             &qb[(size_t)r * HDIM + c4 * 4]);
    }
    {
        const float* kp = kbase + (size_t)(64 * split) * HDIM;
        const float* vp = vbase + (size_t)(64 * split) * HDIM;
#pragma unroll
        for (int i = 0; i < 8; i++) {
            int id = tid + i * 128;
            int r = id >> 4;          // 0..63
            int c4 = id & 15;
            cp16(kb32 + (uint32_t)(r * AQS + c4 * 4) * 4u,
                 &kp[(size_t)r * HDIM + c4 * 4]);
            cp16(vb32 + (uint32_t)(r * AVS + c4 * 4) * 4u,
                 &vp[(size_t)r * HDIM + c4 * 4]);
        }
    }
    CP_COMMIT();

    float O[2][8][4];
#pragma unroll
    for (int m = 0; m < 2; m++)
#pragma unroll
        for (int j = 0; j < 8; j++)
#pragma unroll
            for (int e = 0; e < 4; e++) O[m][j][e] = 0.0f;
    float mrow[2][2] = {{-1e30f, -1e30f}, {-1e30f, -1e30f}};
    float lrow[2][2] = {{0.0f, 0.0f}, {0.0f, 0.0f}};

    const uint32_t* Qu = (const uint32_t*)Qs;
    const uint32_t* Pu = (const uint32_t*)Ps;

    const int kb_last = 2 * t + 1;
    int idx = 0;
    for (int kb = split; kb <= kb_last; kb += 2, idx++) {
        const int cur = idx & 1;
        const bool hn = (kb + 2 <= kb_last);

        CP_WAIT0();
        __syncthreads();

        if (hn) {
            const float* kp = kbase + (size_t)(64 * (kb + 2)) * HDIM;
            const float* vp = vbase + (size_t)(64 * (kb + 2)) * HDIM;
            const uint32_t kn = kb32 + (uint32_t)((cur ^ 1) * KBUF) * 4u;
            const uint32_t vn = vb32 + (uint32_t)((cur ^ 1) * VBUF) * 4u;
#pragma unroll
            for (int i = 0; i < 8; i++) {
                int id = tid + i * 128;
                int r = id >> 4;
                int c4 = id & 15;
                cp16(kn + (uint32_t)(r * AQS + c4 * 4) * 4u,
                     &kp[(size_t)r * HDIM + c4 * 4]);
                cp16(vn + (uint32_t)(r * AVS + c4 * 4) * 4u,
                     &vp[(size_t)r * HDIM + c4 * 4]);
            }
            CP_COMMIT();
        }

        // diagonal bookkeeping
        const bool diag = (kb >= 2 * t);
        const int s64 = diag ? (kb - 2 * t) * 64 : 0;
        const bool skip = diag && (rb + 31 < s64);
        int jmax = 7;
        if (diag) {
            int jm = (rb + 31 - s64) >> 3;
            jmax = jm < 7 ? jm : 7;
        }

        if (!skip) {
            const uint32_t* Ku = (const uint32_t*)(Ks + cur * KBUF);
            const uint32_t* Vu = (const uint32_t*)(Vs + cur * VBUF);

            // ---- S = Q K^T (two m16 subtiles share each K b-frag) ----
            float S[2][8][4];
#pragma unroll
            for (int m = 0; m < 2; m++)
#pragma unroll
                for (int j = 0; j < 8; j++)
#pragma unroll
                    for (int e = 0; e < 4; e++) S[m][j][e] = 0.0f;
#pragma unroll
            for (int ks = 0; ks < 8; ks++) {
                uint32_t a[8];
#pragma unroll
                for (int m = 0; m < 2; m++) {
                    const int rr = rb + 16 * m;
                    a[4 * m + 0] = Qu[(rr + grp) * AQS + 8 * ks + tig];
                    a[4 * m + 1] = Qu[(rr + grp + 8) * AQS + 8 * ks + tig];
                    a[4 * m + 2] = Qu[(rr + grp) * AQS + 8 * ks + tig + 4];
                    a[4 * m + 3] = Qu[(rr + grp + 8) * AQS + 8 * ks + tig + 4];
                }
#pragma unroll
                for (int j = 0; j < 8; j++) {
                    if (j <= jmax) {
                        uint32_t bf[2];
                        bf[0] = Ku[(8 * j + grp) * AQS + 8 * ks + tig];
                        bf[1] = Ku[(8 * j + grp) * AQS + 8 * ks + tig + 4];
                        mma_tf32(S[0][j], a, bf);
                        mma_tf32(S[1][j], a + 4, bf);
                    }
                }
            }

            // ---- mask diagonal ----
            if (diag) {
#pragma unroll
                for (int m = 0; m < 2; m++) {
                    const int rr = rb + 16 * m + grp;
#pragma unroll
                    for (int j = 0; j < 8; j++) {
                        if (j <= jmax) {
#pragma unroll
                            for (int e = 0; e < 2; e++) {
                                int key = s64 + 8 * j + 2 * tig + e;
                                if (key > rr)     S[m][j][e]     = -1e30f;
                                if (key > rr + 8) S[m][j][2 + e] = -1e30f;
                            }
                        }
                    }
                }
            }

            // ---- online softmax (per m-subtile) ----
#pragma unroll
            for (int m = 0; m < 2; m++) {
                float mA = -1e30f, mB = -1e30f;
#pragma unroll
                for (int j = 0; j < 8; j++) {
                    if (j <= jmax) {
                        mA = fmaxf(mA, fmaxf(S[m][j][0], S[m][j][1]));
                        mB = fmaxf(mB, fmaxf(S[m][j][2], S[m][j][3]));
                    }
                }
                mA = qmax(mA); mB = qmax(mB);
                float mnA = fmaxf(mrow[m][0], mA), mnB = fmaxf(mrow[m][1], mB);
                float alA = __expf(mrow[m][0] - mnA), alB = __expf(mrow[m][1] - mnB);
                float sA = 0.0f, sB = 0.0f;
                const int rr = rb + 16 * m + grp;
#pragma unroll
                for (int j = 0; j < 8; j++) {
                    if (j <= jmax) {
                        float p00 = __expf(S[m][j][0] - mnA);
                        float p01 = __expf(S[m][j][1] - mnA);
                        float p10 = __expf(S[m][j][2] - mnB);
                        float p11 = __expf(S[m][j][3] - mnB);
                        sA += p00 + p01; sB += p10 + p11;
                        *(uint2*)&Ps[rr * APS + 8 * j + 2 * tig] =
                            make_uint2(to_tf32(p00), to_tf32(p01));
                        *(uint2*)&Ps[(rr + 8) * APS + 8 * j + 2 * tig] =
                            make_uint2(to_tf32(p10), to_tf32(p11));
                    }
                }
                sA = qsum(sA); sB = qsum(sB);
                lrow[m][0] = lrow[m][0] * alA + sA; mrow[m][0] = mnA;
                lrow[m][1] = lrow[m][1] * alB + sB; mrow[m][1] = mnB;
#pragma unroll
                for (int j = 0; j < 8; j++) {
                    O[m][j][0] *= alA; O[m][j][1] *= alA;
                    O[m][j][2] *= alB; O[m][j][3] *= alB;
                }
            }
            __syncwarp();   // Ps produced/consumed within this warp only

            // ---- O += P @ V (two m16 subtiles share each V b-frag) ----
#pragma unroll
            for (int ks = 0; ks < 8; ks++) {
                if (ks <= jmax) {
                    uint32_t pa[8];
#pragma unroll
                    for (int m = 0; m < 2; m++) {
                        const int rr = rb + 16 * m;
                        pa[4 * m + 0] = Pu[(rr + grp) * APS + 8 * ks + tig];
                        pa[4 * m + 1] = Pu[(rr + grp + 8) * APS + 8 * ks + tig];
                        pa[4 * m + 2] = Pu[(rr + grp) * APS + 8 * ks + tig + 4];
                        pa[4 * m + 3] = Pu[(rr + grp + 8) * APS + 8 * ks + tig + 4];
                    }
#pragma unroll
                    for (int j = 0; j < 8; j++) {
                        uint32_t vb[2];
                        vb[0] = Vu[(8 * ks + tig) * AVS + 8 * j + grp];
                        vb[1] = Vu[(8 * ks + tig + 4) * AVS + 8 * j + grp];
                        mma_tf32(O[0][j], pa, vb);
                        mma_tf32(O[1][j], pa + 4, vb);
                    }
                }
            }
        }
    }

    // ---- write split partials ----
#pragma unroll
    for (int m = 0; m < 2; m++) {
        const size_t row = (size_t)b * SEQ + 128 * t + rb + 16 * m + grp;
#pragma unroll
        for (int j = 0; j < 8; j++) {
            *(float2*)&g_osc[split][row * HDIM + 8 * j + 2 * tig] =
                make_float2(O[m][j][0], O[m][j][1]);
            *(float2*)&g_osc[split][(row + 8) * HDIM + 8 * j + 2 * tig] =
                make_float2(O[m][j][2], O[m][j][3]);
        }
        if (tig == 0) {
            g_ml[split][row * 2]           = mrow[m][0];
            g_ml[split][row * 2 + 1]       = lrow[m][0];
            g_ml[split][(row + 8) * 2]     = mrow[m][1];
            g_ml[split][(row + 8) * 2 + 1] = lrow[m][1];
        }
    }
}

__global__ __launch_bounds__(128) void attn_tc(void)
{
    extern __shared__ float sm[];
    float* Qs = sm;
    float* Ks = Qs + QBUF;
    float* Vs = Ks + 2 * KBUF;
    float* Ps = Vs + 2 * VBUF;

    const uint32_t sbase = (uint32_t)__cvta_generic_to_shared(sm);
    const uint32_t qb32 = sbase;
    const uint32_t kb32 = sbase + (uint32_t)QBUF * 4u;
    const uint32_t vb32 = kb32 + (uint32_t)(2 * KBUF) * 4u;

    const int pair = blockIdx.x;    // 0..15
    const int split = blockIdx.y;   // 0..1
    const int b = blockIdx.z;

    attn_tile_tc(b, pair, split, Qs, Ks, Vs, Ps, qb32, kb32, vb32);
    attn_tile_tc(b, 31 - pair, split, Qs, Ks, Vs, Ps, qb32, kb32, vb32);
}

// ---------------------------------------------------------------------------
// Merge split partials: one float4 per thread
// ---------------------------------------------------------------------------
__global__ __launch_bounds__(256) void merge_kernel(float* __restrict__ out)
{
    const int id = blockIdx.x * 256 + threadIdx.x;
    const size_t row = (size_t)(id >> 4);
    const int c4 = id & 15;
    float m0 = g_ml[0][row * 2], l0 = g_ml[0][row * 2 + 1];
    float m1 = g_ml[1][row * 2], l1 = g_ml[1][row * 2 + 1];
    float mm = fmaxf(m0, m1);
    float w0 = __expf(m0 - mm), w1 = __expf(m1 - mm);
    float inv = 1.0f / (w0 * l0 + w1 * l1);
    w0 *= inv; w1 *= inv;
    float4 a = *(const float4*)&g_osc[0][row * HDIM + c4 * 4];
    float4 c = *(const float4*)&g_osc[1][row * HDIM + c4 * 4];
    float4 o = make_float4(w0 * a.x + w1 * c.x, w0 * a.y + w1 * c.y,
                           w0 * a.z + w1 * c.z, w0 * a.w + w1 * c.w);
    *(float4*)&out[row * HDIM + c4 * 4] = o;
}

// ---------------------------------------------------------------------------
extern "C" void kernel_launch(void* const* d_in, const int* in_sizes, int n_in,
                              void* d_out, int out_size)
{
    const float* x  = (const float*)d_in[0];
    const float* Wk = (const float*)d_in[1];
    const float* Wq = (const float*)d_in[2];
    const float* Wv = (const float*)d_in[3];
    float* out = (float*)d_out;

    cudaFuncSetAttribute(proj_fused, cudaFuncAttributeMaxDynamicSharedMemorySize, FPROJ_SMEM);
    cudaFuncSetAttribute(attn_tc, cudaFuncAttributeMaxDynamicSharedMemorySize, ATTN_SMEM);

    prep_w<<<(CDIM * 192) / 256, 256>>>(Wq, Wk, Wv);
    proj_fused<<<MROWS / 64, 128, FPROJ_SMEM>>>(x);

    dim3 agrid(16, 2, BATCH);
    attn_tc<<<agrid, 128, ATTN_SMEM>>>();

    merge_kernel<<<(MROWS * 16) / 256, 256>>>(out);
}

// round 16
// speedup vs baseline: 1.3979x; 1.3979x over previous
#include <cuda_runtime.h>
#include <cuda_bf16.h>
#include <math.h>
#include <cstdint>

#define BATCH 4
#define SEQ 4096
#define CDIM 1024
#define HDIM 64
#define MROWS (BATCH * SEQ)   // 16384
#define NSPLIT 4

// Scratch (no cudaMalloc allowed). g_q/g_k/g_v hold tf32-rounded floats;
// g_q additionally pre-scaled by 1/sqrt(64). g_wt = [1024][192] tf32 weights.
__device__ float g_q[(size_t)MROWS * HDIM];
__device__ float g_k[(size_t)MROWS * HDIM];
__device__ float g_v[(size_t)MROWS * HDIM];
__device__ float g_wt[(size_t)CDIM * 192];
__device__ float g_osc[NSPLIT][(size_t)MROWS * HDIM];   // split partial O
__device__ float g_ml[NSPLIT][(size_t)MROWS * 2];       // split (m, l)

// ---------------------------------------------------------------------------
// helpers
// ---------------------------------------------------------------------------
__device__ __forceinline__ uint32_t to_tf32(float f) {
    uint32_t r;
    asm("cvt.rna.tf32.f32 %0, %1;" : "=r"(r) : "f"(f));
    return r;
}
__device__ __forceinline__ void mma_tf32(float* c, const uint32_t* a, const uint32_t* b) {
    asm volatile(
        "mma.sync.aligned.m16n8k8.row.col.f32.tf32.tf32.f32 "
        "{%0,%1,%2,%3}, {%4,%5,%6,%7}, {%8,%9}, {%0,%1,%2,%3};\n"
        : "+f"(c[0]), "+f"(c[1]), "+f"(c[2]), "+f"(c[3])
        : "r"(a[0]), "r"(a[1]), "r"(a[2]), "r"(a[3]), "r"(b[0]), "r"(b[1]));
}
__device__ __forceinline__ float qmax(float v) {
    v = fmaxf(v, __shfl_xor_sync(0xffffffffu, v, 1));
    v = fmaxf(v, __shfl_xor_sync(0xffffffffu, v, 2));
    return v;
}
__device__ __forceinline__ float qsum(float v) {
    v += __shfl_xor_sync(0xffffffffu, v, 1);
    v += __shfl_xor_sync(0xffffffffu, v, 2);
    return v;
}
__device__ __forceinline__ void cp16(uint32_t smem_dst, const void* gmem_src) {
    asm volatile("cp.async.cg.shared.global [%0], [%1], 16;"
                 :: "r"(smem_dst), "l"(gmem_src));
}
#define CP_COMMIT() asm volatile("cp.async.commit_group;" ::: "memory")
#define CP_WAIT0()  asm volatile("cp.async.wait_group 0;" ::: "memory")

// ---------------------------------------------------------------------------
// prep_w: convert the three weight matrices to tf32, packed [1024][192]
// ---------------------------------------------------------------------------
__global__ __launch_bounds__(256) void prep_w(
    const float* __restrict__ Wq,
    const float* __restrict__ Wk,
    const float* __restrict__ Wv)
{
    int idx = blockIdx.x * 256 + threadIdx.x;
    int k = idx / 192;
    int c = idx % 192;
    const float* W = (c < 64) ? Wq : (c < 128) ? Wk : Wv;
    g_wt[idx] = __uint_as_float(to_tf32(W[k * HDIM + (c & 63)]));
}

// ---------------------------------------------------------------------------
// Fused projection: {q,k,v} = x @ [Wq|Wk|Wv]  (unchanged from R10)
// ---------------------------------------------------------------------------
#define FAS 36
#define FBS 200
#define FABUF (64 * FAS)
#define FBBUF (32 * FBS)
#define FBUF  (FABUF + FBBUF)
#define FPROJ_SMEM (2 * FBUF * 4)

__global__ __launch_bounds__(128) void proj_fused(const float* __restrict__ x)
{
    extern __shared__ float sm[];
    const uint32_t sbase = (uint32_t)__cvta_generic_to_shared(sm);

    const int tid = threadIdx.x;
    const int warp = tid >> 5;
    const int lane = tid & 31;
    const int grp = lane >> 2;
    const int tig = lane & 3;
    const int wm = warp >> 1;
    const int wn = warp & 1;
    const int row0 = blockIdx.x * 64;

    float acc[2][12][4];
#pragma unroll
    for (int m = 0; m < 2; m++)
#pragma unroll
        for (int j = 0; j < 12; j++)
#pragma unroll
            for (int e = 0; e < 4; e++) acc[m][j][e] = 0.0f;

    auto issue_tile = [&](int it, int buf) {
        const int kc = it * 32;
        const uint32_t ab = sbase + (uint32_t)(buf * FBUF) * 4u;
        const uint32_t bb = ab + (uint32_t)FABUF * 4u;
#pragma unroll
        for (int i = 0; i < 4; i++) {
            int id = tid + i * 128;
            int r = id >> 3;
            int c4 = id & 7;
            cp16(ab + (uint32_t)(r * FAS + c4 * 4) * 4u,
                 &x[(size_t)(row0 + r) * CDIM + kc + c4 * 4]);
        }
#pragma unroll
        for (int i = 0; i < 12; i++) {
            int id = tid + i * 128;
            int r = id / 48;
            int c = id % 48;
            cp16(bb + (uint32_t)(r * FBS + c * 4) * 4u,
                 &g_wt[(size_t)(kc + r) * 192 + c * 4]);
        }
        CP_COMMIT();
    };

    issue_tile(0, 0);

    for (int it = 0; it < 32; it++) {
        const int cur = it & 1;
        CP_WAIT0();
        __syncthreads();
        if (it < 31) issue_tile(it + 1, cur ^ 1);

        const float* As = sm + cur * FBUF;
        const float* Bs = As + FABUF;

#pragma unroll
        for (int ks = 0; ks < 4; ks++) {
            uint32_t a[8];
#pragma unroll
            for (int m = 0; m < 2; m++) {
                const int rb = 32 * wm + 16 * m;
                a[4 * m + 0] = to_tf32(As[(rb + grp) * FAS + 8 * ks + tig]);
                a[4 * m + 1] = to_tf32(As[(rb + grp + 8) * FAS + 8 * ks + tig]);
                a[4 * m + 2] = to_tf32(As[(rb + grp) * FAS + 8 * ks + tig + 4]);
                a[4 * m + 3] = to_tf32(As[(rb + grp + 8) * FAS + 8 * ks + tig + 4]);
            }
#pragma unroll
            for (int jj = 0; jj < 12; jj++) {
                const int col = 96 * wn + 8 * jj;
                uint32_t b[2];
                b[0] = __float_as_uint(Bs[(8 * ks + tig) * FBS + col + grp]);
                b[1] = __float_as_uint(Bs[(8 * ks + tig + 4) * FBS + col + grp]);
                mma_tf32(acc[0][jj], a, b);
                mma_tf32(acc[1][jj], a + 4, b);
            }
        }
        __syncthreads();
    }

#pragma unroll
    for (int m = 0; m < 2; m++) {
        const int row = row0 + 32 * wm + 16 * m + grp;
#pragma unroll
        for (int jj = 0; jj < 12; jj++) {
            const int gc = 96 * wn + 8 * jj;
            const int mat = gc >> 6;
            const int col = (gc & 63) + 2 * tig;
            float* out = (mat == 0) ? g_q : (mat == 1) ? g_k : g_v;
            const float scale = (mat == 0) ? 0.125f : 1.0f;
            float2 lo = make_float2(
                __uint_as_float(to_tf32(scale * acc[m][jj][0])),
                __uint_as_float(to_tf32(scale * acc[m][jj][1])));
            float2 hi = make_float2(
                __uint_as_float(to_tf32(scale * acc[m][jj][2])),
                __uint_as_float(to_tf32(scale * acc[m][jj][3])));
            *(float2*)&out[(size_t)row * HDIM + col] = lo;
            *(float2*)&out[(size_t)(row + 8) * HDIM + col] = hi;
        }
    }
}

// ---------------------------------------------------------------------------
// Attention: 128-row Q tiles, 4 warps x 32 rows (b-frags shared by 2 m16
// subtiles), 32-key double-buffered K/V blocks (smem 105KB -> 2 CTAs/SM).
// Split-4 over kb mod 4 + pair (t, 31-t): every CTA runs exactly 33 key
// blocks -> 256 uniform CTAs of 128 threads (8 warps/SM on 128 SMs).
// 32-key block kb is diagonal for kb in {4t..4t+3}.
// ---------------------------------------------------------------------------
#define AQS 68
#define AVS 72
#define APS 68
#define QBUF (128 * AQS)
#define KBUF (32 * AQS)
#define VBUF (32 * AVS)
#define PBUF (128 * APS)
#define ATTN_SMEM ((QBUF + 2 * KBUF + 2 * VBUF + PBUF) * 4)

__device__ __forceinline__ void attn_tile_tc(
    int b, int t, int split,
    float* Qs, float* Ks, float* Vs, float* Ps,
    uint32_t qb32, uint32_t kb32, uint32_t vb32)
{
    const int tid = threadIdx.x;
    const int mg = tid >> 5;          // warp 0..3 -> rows 32*mg..32*mg+31
    const int lane = tid & 31;
    const int grp = lane >> 2;
    const int tig = lane & 3;
    const int rb = 32 * mg;

    const float* kbase = g_k + (size_t)b * SEQ * HDIM;
    const float* vbase = g_v + (size_t)b * SEQ * HDIM;
    const float* qb = g_q + ((size_t)b * SEQ + 128 * t) * HDIM;

    __syncthreads();   // previous tile done with all smem

    // ---- prologue: Q (128x64) + first K/V (32x64) into buffer 0 ----
#pragma unroll
    for (int i = 0; i < 16; i++) {
        int id = tid + i * 128;
        int r = id >> 4;              // 0..127
        int c4 = id & 15;
        cp16(qb32 + (uint32_t)(r * AQS + c4 * 4) * 4u,
             &qb[(size_t)r * HDIM + c4 * 4]);
    }
    {
        const float* kp = kbase + (size_t)(32 * split) * HDIM;
        const float* vp = vbase + (size_t)(32 * split) * HDIM;
#pragma unroll
        for (int i = 0; i < 4; i++) {
            int id = tid + i * 128;
            int r = id >> 4;          // 0..31
            int c4 = id & 15;
            cp16(kb32 + (uint32_t)(r * AQS + c4 * 4) * 4u,
                 &kp[(size_t)r * HDIM + c4 * 4]);
            cp16(vb32 + (uint32_t)(r * AVS + c4 * 4) * 4u,
                 &vp[(size_t)r * HDIM + c4 * 4]);
        }
    }
    CP_COMMIT();

    float O[2][8][4];
#pragma unroll
    for (int m = 0; m < 2; m++)
#pragma unroll
        for (int j = 0; j < 8; j++)
#pragma unroll
            for (int e = 0; e < 4; e++) O[m][j][e] = 0.0f;
    float mrow[2][2] = {{-1e30f, -1e30f}, {-1e30f, -1e30f}};
    float lrow[2][2] = {{0.0f, 0.0f}, {0.0f, 0.0f}};

    const uint32_t* Qu = (const uint32_t*)Qs;
    const uint32_t* Pu = (const uint32_t*)Ps;

    const int kb_last = 4 * t + 3;    // last 32-key block for this tile
    int idx = 0;
    for (int kb = split; kb <= kb_last; kb += NSPLIT, idx++) {
        const int cur = idx & 1;
        const bool hn = (kb + NSPLIT <= kb_last);

        CP_WAIT0();
        __syncthreads();

        if (hn) {
            const float* kp = kbase + (size_t)(32 * (kb + NSPLIT)) * HDIM;
            const float* vp = vbase + (size_t)(32 * (kb + NSPLIT)) * HDIM;
            const uint32_t kn = kb32 + (uint32_t)((cur ^ 1) * KBUF) * 4u;
            const uint32_t vn = vb32 + (uint32_t)((cur ^ 1) * VBUF) * 4u;
#pragma unroll
            for (int i = 0; i < 4; i++) {
                int id = tid + i * 128;
                int r = id >> 4;
                int c4 = id & 15;
                cp16(kn + (uint32_t)(r * AQS + c4 * 4) * 4u,
                     &kp[(size_t)r * HDIM + c4 * 4]);
                cp16(vn + (uint32_t)(r * AVS + c4 * 4) * 4u,
                     &vp[(size_t)r * HDIM + c4 * 4]);
            }
            CP_COMMIT();
        }

        // diagonal bookkeeping: block kb covers local keys [32(kb-4t), +32)
        const bool diag = (kb >= 4 * t);
        const int s32 = diag ? (kb - 4 * t) * 32 : 0;
        const bool skip = diag && (rb + 31 < s32);
        int jmax = 3;
        if (diag) {
            int jm = (rb + 31 - s32) >> 3;
            jmax = jm < 3 ? jm : 3;
        }

        if (!skip) {
            const uint32_t* Ku = (const uint32_t*)(Ks + cur * KBUF);
            const uint32_t* Vu = (const uint32_t*)(Vs + cur * VBUF);

            // ---- S = Q K^T (k-dim = hdim 64: ks 0..7; key j-tiles 0..3) ----
            float S[2][4][4];
#pragma unroll
            for (int m = 0; m < 2; m++)
#pragma unroll
                for (int j = 0; j < 4; j++)
#pragma unroll
                    for (int e = 0; e < 4; e++) S[m][j][e] = 0.0f;
#pragma unroll
            for (int ks = 0; ks < 8; ks++) {
                uint32_t a[8];
#pragma unroll
                for (int m = 0; m < 2; m++) {
                    const int rr = rb + 16 * m;
                    a[4 * m + 0] = Qu[(rr + grp) * AQS + 8 * ks + tig];
                    a[4 * m + 1] = Qu[(rr + grp + 8) * AQS + 8 * ks + tig];
                    a[4 * m + 2] = Qu[(rr + grp) * AQS + 8 * ks + tig + 4];
                    a[4 * m + 3] = Qu[(rr + grp + 8) * AQS + 8 * ks + tig + 4];
                }
#pragma unroll
                for (int j = 0; j < 4; j++) {
                    if (j <= jmax) {
                        uint32_t bf[2];
                        bf[0] = Ku[(8 * j + grp) * AQS + 8 * ks + tig];
                        bf[1] = Ku[(8 * j + grp) * AQS + 8 * ks + tig + 4];
                        mma_tf32(S[0][j], a, bf);
                        mma_tf32(S[1][j], a + 4, bf);
                    }
                }
            }

            // ---- mask diagonal ----
            if (diag) {
#pragma unroll
                for (int m = 0; m < 2; m++) {
                    const int rr = rb + 16 * m + grp;
#pragma unroll
                    for (int j = 0; j < 4; j++) {
                        if (j <= jmax) {
#pragma unroll
                            for (int e = 0; e < 2; e++) {
                                int key = s32 + 8 * j + 2 * tig + e;
                                if (key > rr)     S[m][j][e]     = -1e30f;
                                if (key > rr + 8) S[m][j][2 + e] = -1e30f;
                            }
                        }
                    }
                }
            }

            // ---- online softmax (per m-subtile) ----
#pragma unroll
            for (int m = 0; m < 2; m++) {
                float mA = -1e30f, mB = -1e30f;
#pragma unroll
                for (int j = 0; j < 4; j++) {
                    if (j <= jmax) {
                        mA = fmaxf(mA, fmaxf(S[m][j][0], S[m][j][1]));
                        mB = fmaxf(mB, fmaxf(S[m][j][2], S[m][j][3]));
                    }
                }
                mA = qmax(mA); mB = qmax(mB);
                float mnA = fmaxf(mrow[m][0], mA), mnB = fmaxf(mrow[m][1], mB);
                float alA = __expf(mrow[m][0] - mnA), alB = __expf(mrow[m][1] - mnB);
                float sA = 0.0f, sB = 0.0f;
                const int rr = rb + 16 * m + grp;
#pragma unroll
                for (int j = 0; j < 4; j++) {
                    if (j <= jmax) {
                        float p00 = __expf(S[m][j][0] - mnA);
                        float p01 = __expf(S[m][j][1] - mnA);
                        float p10 = __expf(S[m][j][2] - mnB);
                        float p11 = __expf(S[m][j][3] - mnB);
                        sA += p00 + p01; sB += p10 + p11;
                        *(uint2*)&Ps[rr * APS + 8 * j + 2 * tig] =
                            make_uint2(to_tf32(p00), to_tf32(p01));
                        *(uint2*)&Ps[(rr + 8) * APS + 8 * j + 2 * tig] =
                            make_uint2(to_tf32(p10), to_tf32(p11));
                    }
                }
                sA = qsum(sA); sB = qsum(sB);
                lrow[m][0] = lrow[m][0] * alA + sA; mrow[m][0] = mnA;
                lrow[m][1] = lrow[m][1] * alB + sB; mrow[m][1] = mnB;
#pragma unroll
                for (int j = 0; j < 8; j++) {
                    O[m][j][0] *= alA; O[m][j][1] *= alA;
                    O[m][j][2] *= alB; O[m][j][3] *= alB;
                }
            }
            __syncwarp();   // Ps produced/consumed within this warp only

            // ---- O += P @ V (k-dim = 32 keys: ks 0..3; hdim j-tiles 0..7) ----
#pragma unroll
            for (int ks = 0; ks < 4; ks++) {
                if (ks <= jmax) {
                    uint32_t pa[8];
#pragma unroll
                    for (int m = 0; m < 2; m++) {
                        const int rr = rb + 16 * m;
                        pa[4 * m + 0] = Pu[(rr + grp) * APS + 8 * ks + tig];
                        pa[4 * m + 1] = Pu[(rr + grp + 8) * APS + 8 * ks + tig];
                        pa[4 * m + 2] = Pu[(rr + grp) * APS + 8 * ks + tig + 4];
                        pa[4 * m + 3] = Pu[(rr + grp + 8) * APS + 8 * ks + tig + 4];
                    }
#pragma unroll
                    for (int j = 0; j < 8; j++) {
                        uint32_t vb[2];
                        vb[0] = Vu[(8 * ks + tig) * AVS + 8 * j + grp];
                        vb[1] = Vu[(8 * ks + tig + 4) * AVS + 8 * j + grp];
                        mma_tf32(O[0][j], pa, vb);
                        mma_tf32(O[1][j], pa + 4, vb);
                    }
                }
            }
        }
    }

    // ---- write split partials ----
#pragma unroll
    for (int m = 0; m < 2; m++) {
        const size_t row = (size_t)b * SEQ + 128 * t + rb + 16 * m + grp;
#pragma unroll
        for (int j = 0; j < 8; j++) {
            *(float2*)&g_osc[split][row * HDIM + 8 * j + 2 * tig] =
                make_float2(O[m][j][0], O[m][j][1]);
            *(float2*)&g_osc[split][(row + 8) * HDIM + 8 * j + 2 * tig] =
                make_float2(O[m][j][2], O[m][j][3]);
        }
        if (tig == 0) {
            g_ml[split][row * 2]           = mrow[m][0];
            g_ml[split][row * 2 + 1]       = lrow[m][0];
            g_ml[split][(row + 8) * 2]     = mrow[m][1];
            g_ml[split][(row + 8) * 2 + 1] = lrow[m][1];
        }
    }
}

__global__ __launch_bounds__(128) void attn_tc(void)
{
    extern __shared__ float sm[];
    float* Qs = sm;
    float* Ks = Qs + QBUF;
    float* Vs = Ks + 2 * KBUF;
    float* Ps = Vs + 2 * VBUF;

    const uint32_t sbase = (uint32_t)__cvta_generic_to_shared(sm);
    const uint32_t qb32 = sbase;
    const uint32_t kb32 = sbase + (uint32_t)QBUF * 4u;
    const uint32_t vb32 = kb32 + (uint32_t)(2 * KBUF) * 4u;

    const int pair = blockIdx.x;    // 0..15
    const int split = blockIdx.y;   // 0..3
    const int b = blockIdx.z;

    attn_tile_tc(b, pair, split, Qs, Ks, Vs, Ps, qb32, kb32, vb32);
    attn_tile_tc(b, 31 - pair, split, Qs, Ks, Vs, Ps, qb32, kb32, vb32);
}

// ---------------------------------------------------------------------------
// Merge 4 split partials: one float4 per thread
// ---------------------------------------------------------------------------
__global__ __launch_bounds__(256) void merge_kernel(float* __restrict__ out)
{
    const int id = blockIdx.x * 256 + threadIdx.x;
    const size_t row = (size_t)(id >> 4);
    const int c4 = id & 15;

    float m[NSPLIT], l[NSPLIT];
#pragma unroll
    for (int s = 0; s < NSPLIT; s++) {
        m[s] = g_ml[s][row * 2];
        l[s] = g_ml[s][row * 2 + 1];
    }
    float mm = m[0];
#pragma unroll
    for (int s = 1; s < NSPLIT; s++) mm = fmaxf(mm, m[s]);
    float w[NSPLIT], den = 0.0f;
#pragma unroll
    for (int s = 0; s < NSPLIT; s++) {
        w[s] = __expf(m[s] - mm);
        den += w[s] * l[s];
    }
    float inv = 1.0f / den;

    float4 o = make_float4(0.f, 0.f, 0.f, 0.f);
#pragma unroll
    for (int s = 0; s < NSPLIT; s++) {
        float ws = w[s] * inv;
        float4 a = *(const float4*)&g_osc[s][row * HDIM + c4 * 4];
        o.x += ws * a.x; o.y += ws * a.y; o.z += ws * a.z; o.w += ws * a.w;
    }
    *(float4*)&out[row * HDIM + c4 * 4] = o;
}

// ---------------------------------------------------------------------------
extern "C" void kernel_launch(void* const* d_in, const int* in_sizes, int n_in,
                              void* d_out, int out_size)
{
    const float* x  = (const float*)d_in[0];
    const float* Wk = (const float*)d_in[1];
    const float* Wq = (const float*)d_in[2];
    const float* Wv = (const float*)d_in[3];
    float* out = (float*)d_out;

    cudaFuncSetAttribute(proj_fused, cudaFuncAttributeMaxDynamicSharedMemorySize, FPROJ_SMEM);
    cudaFuncSetAttribute(attn_tc, cudaFuncAttributeMaxDynamicSharedMemorySize, ATTN_SMEM);

    prep_w<<<(CDIM * 192) / 256, 256>>>(Wq, Wk, Wv);
    proj_fused<<<MROWS / 64, 128, FPROJ_SMEM>>>(x);

    dim3 agrid(16, NSPLIT, BATCH);
    attn_tc<<<agrid, 128, ATTN_SMEM>>>();

    merge_kernel<<<(MROWS * 16) / 256, 256>>>(out);
}